// round 6
// baseline (speedup 1.0000x reference)
#include <cuda_runtime.h>
#include <stdint.h>

// Problem shape (fixed by the reference): x is (T, B, 1) fp32, lr scalar.
#define T_DIM 8192
#define B_DIM 4096
#define S_CHUNKS 64
#define CH 128            // T_DIM / S_CHUNKS
#define NWORDS 4          // CH / 32
#define NTILES (B_DIM / 256)   // 16 column tiles of 256

// Scratch (device globals — no allocation allowed).
__device__ float2   g_state[S_CHUNKS * B_DIM];          // entry (p0,p1) per (s,b)  2 MB
__device__ unsigned g_flag [S_CHUNKS * NTILES];         // entry-state-ready flags
__device__ unsigned g_ticket;

__device__ __forceinline__ float clamp_lr(const float* lrp) {
    return fminf(fmaxf(*lrp, 0.0f), 1.0f);
}

// r^n, n in [0,128], square-and-multiply (no smem, no sync).
__device__ __forceinline__ float rpow_int(float r, int n) {
    float res = 1.0f, base = r;
    #pragma unroll
    for (int i = 0; i < 8; i++) {
        res  = ((n >> i) & 1) ? res * base : res;
        base = base * base;
    }
    return res;
}

__device__ __forceinline__ unsigned ld_acquire(const unsigned* p) {
    unsigned v;
    asm volatile("ld.acquire.gpu.u32 %0, [%1];" : "=r"(v) : "l"(p) : "memory");
    return v;
}
__device__ __forceinline__ void st_release(unsigned* p, unsigned v) {
    asm volatile("st.release.gpu.u32 [%0], %1;" :: "l"(p), "r"(v) : "memory");
}

__global__ void init_kernel() {
    const int i = blockIdx.x * blockDim.x + threadIdx.x;
    if (i < S_CHUNKS * NTILES) g_flag[i] = 0u;
    if (i == 0) g_ticket = 0u;
}

// ---------------------------------------------------------------------------
// Fused kernel. Each block = (chunk s, 256-column tile bx), assigned via an
// atomic ticket in s-major order (deadlock-free chained waiting).
// Phase 1 (parallel across all blocks): stream the x chunk once, pack bits
//   into registers W[4], accumulate additive terms C0/C1; multiplier A = r^n
//   via popcount of the obs_prev bit stream.
// Phase 2 (chain): wait for entry state from chunk s-1 tile, compute exit
//   state with 2 FMAs, publish it immediately (release) — replay is NOT on
//   the chain's critical path.
// Phase 3: replay the chunk from register bits and stream predictions out.
// x is read exactly once from HBM; out written exactly once; no bits/coefs
// ever round-trip through memory.
// ---------------------------------------------------------------------------
__global__ void __launch_bounds__(256) fused_kernel(
    const float* __restrict__ x, const float* __restrict__ lrp,
    float* __restrict__ out)
{
    __shared__ unsigned s_ticket;
    if (threadIdx.x == 0) s_ticket = atomicAdd(&g_ticket, 1u);
    __syncthreads();
    const int s  = s_ticket >> 4;          // s-major: all chunk-0 tiles first
    const int bx = s_ticket & (NTILES - 1);
    const int b  = bx * 256 + threadIdx.x;

    const float lr = clamp_lr(lrp);
    const float r  = 1.0f - lr;

    // ---- Phase 1: load + local affine (identical math to R4 pass1) ----
    const float* xp = x + (size_t)(s * CH) * B_DIM + b;
    const float xprev = (s == 0) ? 0.0f : xp[-(ptrdiff_t)B_DIM];
    bool pb = (xprev != 0.0f);

    float C0 = 0.0f, C1 = 0.0f;
    uint32_t W[NWORDS];

    #pragma unroll
    for (int h = 0; h < NWORDS; h++) {
        uint32_t w = 0;
        #pragma unroll
        for (int i0 = 0; i0 < 32; i0 += 8) {
            float xv[8];                              // 8-deep LDG batch
            #pragma unroll
            for (int j = 0; j < 8; j++)
                xv[j] = xp[(size_t)(h * 32 + i0 + j) * B_DIM];
            #pragma unroll
            for (int j = 0; j < 8; j++) {
                const float v  = xv[j];
                const bool  xb = (v != 0.0f);
                const float t  = v * lr;              // exact: x in {0,1}
                C0 = pb ? C0 : fmaf(C0, r, t);
                C1 = pb ? fmaf(C1, r, t) : C1;
                w  = xb ? (w | (1u << (i0 + j))) : w;
                pb = xb;
            }
        }
        W[h] = w;
    }

    // obs_prev stream over the chunk = [xprev, x_0 .. x_126]
    const int ones = __popc(W[0]) + __popc(W[1]) + __popc(W[2]) + __popc(W[3]);
    const int n1   = ones - (int)(W[3] >> 31) + (xprev != 0.0f ? 1 : 0);
    const float A0 = rpow_int(r, CH - n1);
    const float A1 = rpow_int(r, n1);

    // ---- Phase 2: chain — receive entry state, publish exit state ----
    float p0, p1;
    if (s == 0) {
        p0 = 0.5f; p1 = 0.5f;
    } else {
        if (threadIdx.x == 0) {
            while (ld_acquire(&g_flag[(s - 1) * NTILES + bx]) == 0u)
                __nanosleep(64);
        }
        __syncthreads();                               // acquire -> whole block
        const float2 st = g_state[(s - 1) * B_DIM + b];
        p0 = st.x; p1 = st.y;
    }
    if (s < S_CHUNKS - 1) {
        g_state[s * B_DIM + b] = make_float2(fmaf(p0, A0, C0), fmaf(p1, A1, C1));
        __syncthreads();                               // all stores done
        if (threadIdx.x == 0)
            st_release(&g_flag[s * NTILES + bx], 1u);  // publish
    }

    // ---- Phase 3: replay from register bits, stream out (R1 pass2 math) ----
    float* op = out + (size_t)(s * CH) * B_DIM + b;
    bool pb2 = (xprev != 0.0f);
    #pragma unroll
    for (int wi = 0; wi < NWORDS; wi++) {
        uint32_t w = W[wi];
        #pragma unroll
        for (int i = 0; i < 32; i++) {
            const bool  xb = (w & 1u);
            w >>= 1;
            const float xv = xb ? 1.0f : 0.0f;
            const float l0 = pb2 ? 0.0f : lr;
            const float l1 = pb2 ? lr   : 0.0f;
            p0 = fmaf(l0, xv - p0, p0);
            p1 = fmaf(l1, xv - p1, p1);
            op[(size_t)(wi * 32 + i) * B_DIM] = xb ? p1 : p0;
            pb2 = xb;
        }
    }
}

extern "C" void kernel_launch(void* const* d_in, const int* in_sizes, int n_in,
                              void* d_out, int out_size)
{
    const float* x  = (const float*)d_in[0];
    const float* lr = (const float*)d_in[1];
    if (n_in >= 2 && in_sizes[0] == 1) { x = (const float*)d_in[1]; lr = (const float*)d_in[0]; }

    init_kernel<<<(S_CHUNKS * NTILES + 255) / 256, 256>>>();
    fused_kernel<<<S_CHUNKS * NTILES, 256>>>(x, lr, (float*)d_out);
}